// round 5
// baseline (speedup 1.0000x reference)
#include <cuda_runtime.h>
#include <cuda_bf16.h>
#include <math.h>

#define NB 32
#define NN 512
#define DD 256
#define INV_EPS 10.0f
#define TINYF 1e-16f
#define MARG (1.0f/512.0f)
#define ITERS 15
#define PGRID 128      // persistent grid: 4 blocks per batch, 1 block/SM
#define PTHREADS 1024

// ---------------- scratch (static __device__; no allocations) ----------------
static __device__ float g_rx[NB*NN];                     // 1/|x_row|
static __device__ float g_ry[NB*NN];                     // 1/|y_row|
static __device__ float g_E [(size_t)NB*NN*NN];          // 32 MB  E = exp(-C/eps) fp32
static __device__ float g_colpart[2][PGRID][NN];         // double-buffered col partials
static __device__ float g_cpart[PGRID];                  // per-block cost partials
static __device__ int   g_flag[ITERS][PGRID];            // per-iteration release flags

// ---------------- 1) reciprocal row norms of x and y --------------------------
__global__ void norm_kernel(const float* __restrict__ x, const float* __restrict__ y) {
    int gw   = (blockIdx.x * blockDim.x + threadIdx.x) >> 5;
    int lane = threadIdx.x & 31;
    const float* src; float* dst; int row;
    if (gw < NB*NN) { src = x; dst = g_rx; row = gw; }
    else            { src = y; dst = g_ry; row = gw - NB*NN; }
    const float4* s4 = (const float4*)(src + (size_t)row * DD);
    float4 a = s4[lane];
    float4 b = s4[lane + 32];
    float ss = a.x*a.x + a.y*a.y + a.z*a.z + a.w*a.w
             + b.x*b.x + b.y*b.y + b.z*b.z + b.w*b.w;
    #pragma unroll
    for (int o = 16; o; o >>= 1) ss += __shfl_xor_sync(0xffffffffu, ss, o);
    if (lane == 0) dst[row] = rsqrtf(ss);   // norms ~16; 1e-8 clamp never binds
}

// ---------------- 2) tf32 tensor-core GEMM: C = 1 - (x/|x|)(y/|y|)^T ---------
__device__ __forceinline__ unsigned f2tf32(float f) {
    unsigned r;
    asm("cvt.rna.tf32.f32 %0, %1;" : "=r"(r) : "f"(f));
    return r;
}

__global__ void __launch_bounds__(256) gemm_kernel(float* __restrict__ Cout,
                                                   const float* __restrict__ x,
                                                   const float* __restrict__ y) {
    __shared__ float As[128][36];
    __shared__ float Bs[64][36];
    int b  = blockIdx.z;
    int m0 = blockIdx.y * 128, n0 = blockIdx.x * 64;
    const float* A = x + (size_t)b * NN * DD;
    const float* B = y + (size_t)b * NN * DD;
    int t = threadIdx.x, lane = t & 31, warp = t >> 5;
    int wm = (warp >> 1) * 32;
    int wn = (warp & 1) * 32;
    int lr = t >> 3;
    int lc = (t & 7) * 4;

    float ra[4], rb[2];
    #pragma unroll
    for (int i = 0; i < 4; i++) ra[i] = g_rx[b*NN + m0 + lr + 32*i];
    #pragma unroll
    for (int i = 0; i < 2; i++) rb[i] = g_ry[b*NN + n0 + lr + 32*i];

    float acc[2][4][4];
    #pragma unroll
    for (int i=0;i<2;i++)
        #pragma unroll
        for (int j=0;j<4;j++)
            #pragma unroll
            for (int k=0;k<4;k++) acc[i][j][k] = 0.f;

    for (int k0 = 0; k0 < DD; k0 += 32) {
        #pragma unroll
        for (int i = 0; i < 4; i++) {
            float4 v = *(const float4*)(A + (size_t)(m0 + lr + 32*i) * DD + k0 + lc);
            float4 w;
            w.x = __uint_as_float(f2tf32(v.x * ra[i])); w.y = __uint_as_float(f2tf32(v.y * ra[i]));
            w.z = __uint_as_float(f2tf32(v.z * ra[i])); w.w = __uint_as_float(f2tf32(v.w * ra[i]));
            *(float4*)&As[lr + 32*i][lc] = w;
        }
        #pragma unroll
        for (int i = 0; i < 2; i++) {
            float4 v = *(const float4*)(B + (size_t)(n0 + lr + 32*i) * DD + k0 + lc);
            float4 w;
            w.x = __uint_as_float(f2tf32(v.x * rb[i])); w.y = __uint_as_float(f2tf32(v.y * rb[i]));
            w.z = __uint_as_float(f2tf32(v.z * rb[i])); w.w = __uint_as_float(f2tf32(v.w * rb[i]));
            *(float4*)&Bs[lr + 32*i][lc] = w;
        }
        __syncthreads();
        #pragma unroll
        for (int s = 0; s < 4; s++) {
            int kc = s * 8 + (lane & 3);
            unsigned bf[4][2];
            #pragma unroll
            for (int nt = 0; nt < 4; nt++) {
                int nb = wn + nt*8 + (lane >> 2);
                bf[nt][0] = __float_as_uint(Bs[nb][kc]);
                bf[nt][1] = __float_as_uint(Bs[nb][kc + 4]);
            }
            #pragma unroll
            for (int mt = 0; mt < 2; mt++) {
                int ma = wm + mt*16 + (lane >> 2);
                unsigned a0 = __float_as_uint(As[ma    ][kc]);
                unsigned a1 = __float_as_uint(As[ma + 8][kc]);
                unsigned a2 = __float_as_uint(As[ma    ][kc + 4]);
                unsigned a3 = __float_as_uint(As[ma + 8][kc + 4]);
                #pragma unroll
                for (int nt = 0; nt < 4; nt++) {
                    asm volatile(
                        "mma.sync.aligned.m16n8k8.row.col.f32.tf32.tf32.f32 "
                        "{%0,%1,%2,%3}, {%4,%5,%6,%7}, {%8,%9}, {%0,%1,%2,%3};"
                        : "+f"(acc[mt][nt][0]), "+f"(acc[mt][nt][1]),
                          "+f"(acc[mt][nt][2]), "+f"(acc[mt][nt][3])
                        : "r"(a0), "r"(a1), "r"(a2), "r"(a3),
                          "r"(bf[nt][0]), "r"(bf[nt][1]));
                }
            }
        }
        __syncthreads();
    }

    size_t base = (size_t)b * NN * NN;
    #pragma unroll
    for (int mt = 0; mt < 2; mt++) {
        #pragma unroll
        for (int nt = 0; nt < 4; nt++) {
            int m = m0 + wm + mt*16 + (lane >> 2);
            int n = n0 + wn + nt*8 + (lane & 3)*2;
            float c0 = 1.0f - acc[mt][nt][0];
            float c1 = 1.0f - acc[mt][nt][1];
            float c2 = 1.0f - acc[mt][nt][2];
            float c3 = 1.0f - acc[mt][nt][3];
            *(float2*)&Cout[base + (size_t)m*NN + n]     = make_float2(c0, c1);
            *(float2*)&g_E [base + (size_t)m*NN + n]     = make_float2(__expf(-INV_EPS*c0), __expf(-INV_EPS*c1));
            *(float2*)&Cout[base + (size_t)(m+8)*NN + n] = make_float2(c2, c3);
            *(float2*)&g_E [base + (size_t)(m+8)*NN + n] = make_float2(__expf(-INV_EPS*c2), __expf(-INV_EPS*c3));
        }
    }
}

// ---------------- 3) reset flags ---------------------------------------------
__global__ void init_kernel() {
    int i = blockIdx.x * blockDim.x + threadIdx.x;
    if (i < ITERS * PGRID) ((int*)g_flag)[i] = 0;
}

// ---------------- 4) persistent Sinkhorn kernel (1024 threads) ---------------
// 128 blocks, 1/SM; block g: batch b=g/4, rows [ (g&3)*128, +128 ).
// E tile cached in smem as bf16 (128KB); 32 warps, 4 rows each.
#define SM_E     0
#define SM_COLP  (131072)                    // 32*512*4 = 65536
#define SM_COLR  (SM_COLP + 65536)           // 2*512*4  = 4096
#define SM_W     (SM_COLR + 4096)
#define SM_Q     (SM_W + 2048)
#define SM_P     (SM_Q + 2048)
#define SM_SU    (SM_P + 512)
#define SM_CRED  (SM_SU + 512)
#define SM_TOT   (SM_CRED + 128 + 64)

__global__ void __launch_bounds__(PTHREADS, 1) sink_kernel(float* __restrict__ pi,
                                                           const float* __restrict__ C) {
    extern __shared__ unsigned char sm[];
    unsigned* Eu  = (unsigned*)(sm + SM_E);      // [128][256] words (2 bf16/word)
    float* colp   = (float*)(sm + SM_COLP);      // [32][512]
    float* colr   = (float*)(sm + SM_COLR);      // [2][512]
    float* w      = (float*)(sm + SM_W);         // [512]
    float* q      = (float*)(sm + SM_Q);         // [512]
    float* p      = (float*)(sm + SM_P);         // [128]
    float* su     = (float*)(sm + SM_SU);        // [128]
    float* cred   = (float*)(sm + SM_CRED);      // [32]

    int g = blockIdx.x, b = g >> 2;
    int row0 = (g & 3) * 128;
    int t = threadIdx.x, warp = t >> 5, lane = t & 31;
    const float* Eg = g_E + ((size_t)b * NN + row0) * NN;

    // prologue: fp32 E -> bf16 smem
    for (int i = t; i < 128*512/4; i += PTHREADS) {
        float4 v = *(const float4*)(Eg + (size_t)i * 4);
        __nv_bfloat162 lo = __floats2bfloat162_rn(v.x, v.y);
        __nv_bfloat162 hi = __floats2bfloat162_rn(v.z, v.w);
        uint2 pk;
        pk.x = *(unsigned*)&lo;
        pk.y = *(unsigned*)&hi;
        *(uint2*)&Eu[i*2] = pk;
    }
    if (t < 512) { w[t] = 1.f; q[t] = 1.f; }
    if (t < 128) p[t] = 1.f;
    __syncthreads();

    for (int it = 0; it < ITERS; it++) {
        // lane owns column pairs {2*lane + 64k, 2*lane+64k+1}, k=0..7
        float wreg[16];
        #pragma unroll
        for (int k = 0; k < 8; k++) {
            float2 wp = *(const float2*)&w[2*lane + 64*k];
            wreg[2*k] = wp.x; wreg[2*k+1] = wp.y;
        }
        float colacc[16];
        #pragma unroll
        for (int i = 0; i < 16; i++) colacc[i] = 0.f;

        #pragma unroll
        for (int r = 0; r < 4; r++) {
            int row = warp * 4 + r;
            const unsigned* Er = &Eu[row * 256];
            // pass 1: streamed dot (4 accumulators, no e[] materialization)
            float d0 = 0.f, d1 = 0.f, d2 = 0.f, d3 = 0.f;
            #pragma unroll
            for (int k = 0; k < 8; k += 2) {
                unsigned wa = Er[lane + 32*k];
                unsigned wb = Er[lane + 32*(k+1)];
                d0 += __uint_as_float(wa << 16)          * wreg[2*k];
                d1 += __uint_as_float(wa & 0xffff0000u)  * wreg[2*k+1];
                d2 += __uint_as_float(wb << 16)          * wreg[2*k+2];
                d3 += __uint_as_float(wb & 0xffff0000u)  * wreg[2*k+3];
            }
            float d = (d0 + d1) + (d2 + d3);
            #pragma unroll
            for (int o = 16; o; o >>= 1) d += __shfl_xor_sync(0xffffffffu, d, o);
            float pold = p[row];
            float un = MARG / (pold * d + TINYF);
            float pn = pold * un;
            if (lane == 0) {
                p[row] = pn;
                if (it == ITERS - 1) su[row] = un * pn;   // u_final * p_final
            }
            // pass 2: streamed column accumulation (reload E from smem)
            #pragma unroll
            for (int k = 0; k < 8; k++) {
                unsigned wd = Er[lane + 32*k];
                colacc[2*k]   += __uint_as_float(wd << 16)         * pn;
                colacc[2*k+1] += __uint_as_float(wd & 0xffff0000u) * pn;
            }
        }
        // stage per-warp column partials
        #pragma unroll
        for (int k = 0; k < 8; k++)
            *(float2*)&colp[warp * 512 + 2*lane + 64*k] =
                make_float2(colacc[2*k], colacc[2*k+1]);
        __syncthreads();
        // two-level block column reduce
        {
            int col = t & 511, h = t >> 9;
            float s = 0.f;
            #pragma unroll
            for (int j = 0; j < 16; j++) s += colp[(h*16 + j) * 512 + col];
            colr[h * 512 + col] = s;
        }
        __syncthreads();
        if (t < 512)
            __stcg(&g_colpart[it & 1][g][t], colr[t] + colr[512 + t]);
        __syncthreads();
        // release flag, then poll the 4 sibling flags in parallel
        if (t == 0) { __threadfence(); __stcg(&g_flag[it][g], 1); }
        if (t < 4) {
            volatile int* f = &g_flag[it][b*4 + t];
            while (*f == 0) __nanosleep(32);
            __threadfence();
        }
        __syncthreads();
        // column update (computed redundantly per block -> deterministic)
        if (t < 512) {
            const float* cp = &g_colpart[it & 1][0][0];
            int b4 = b * 4;
            float tot = __ldcg(&cp[(b4+0)*NN + t]) + __ldcg(&cp[(b4+1)*NN + t])
                      + __ldcg(&cp[(b4+2)*NN + t]) + __ldcg(&cp[(b4+3)*NN + t]);
            float qold = q[t];
            float v = MARG / (qold * tot + TINYF);
            float qn = qold * v;
            q[t] = qn;
            w[t] = qn * v;      // w = v*q (svs for the final pass next iter / epilogue)
        }
        __syncthreads();
    }

    // final: pi = Efp32 * su[row] * w[col]; cost partial
    size_t base = ((size_t)b * NN + row0) * NN;
    float csum = 0.f;
    #pragma unroll
    for (int r = 0; r < 4; r++) {
        int row = warp * 4 + r;
        float s_u = su[row];
        const float4* E4 = (const float4*)(g_E + base + (size_t)row * NN);
        const float4* C4 = (const float4*)(C   + base + (size_t)row * NN);
        float4*       P4 = (float4*)      (pi  + base + (size_t)row * NN);
        #pragma unroll
        for (int k = 0; k < 4; k++) {
            int idx = lane + 32*k;
            float4 e  = E4[idx];
            float4 cc = C4[idx];
            int c0 = idx * 4;
            float4 pv;
            pv.x = e.x * s_u * w[c0+0];
            pv.y = e.y * s_u * w[c0+1];
            pv.z = e.z * s_u * w[c0+2];
            pv.w = e.w * s_u * w[c0+3];
            csum += pv.x*cc.x + pv.y*cc.y + pv.z*cc.z + pv.w*cc.w;
            P4[idx] = pv;
        }
    }
    #pragma unroll
    for (int o = 16; o; o >>= 1) csum += __shfl_xor_sync(0xffffffffu, csum, o);
    if (lane == 0) cred[warp] = csum;
    __syncthreads();
    if (t == 0) {
        float s = 0.f;
        #pragma unroll
        for (int i = 0; i < 32; i++) s += cred[i];
        g_cpart[g] = s;
    }
}

// ---------------- 5) reduce cost partials ------------------------------------
__global__ void cost_kernel(float* __restrict__ cost) {
    int b = threadIdx.x;
    if (b < NB) {
        float s = 0.f;
        #pragma unroll
        for (int k = 0; k < 4; k++) s += g_cpart[b*4 + k];
        cost[b] = s;
    }
}

// ---------------- launch ------------------------------------------------------
extern "C" void kernel_launch(void* const* d_in, const int* in_sizes, int n_in,
                              void* d_out, int out_size) {
    const float* x = (const float*)d_in[0];
    const float* y = (const float*)d_in[1];
    float* out  = (float*)d_out;
    float* cost = out;
    float* pi   = out + NB;
    float* C    = out + NB + (size_t)NB * NN * NN;

    static int smem_set = 0;
    if (!smem_set) {
        cudaFuncSetAttribute(sink_kernel,
                             cudaFuncAttributeMaxDynamicSharedMemorySize, SM_TOT);
        smem_set = 1;
    }

    norm_kernel<<<4096, 256>>>(x, y);
    gemm_kernel<<<dim3(8, 4, NB), 256>>>(C, x, y);
    init_kernel<<<4, 512>>>();
    sink_kernel<<<PGRID, PTHREADS, SM_TOT>>>(pi, C);
    cost_kernel<<<1, 32>>>(cost);
}

// round 7
// speedup vs baseline: 1.4498x; 1.4498x over previous
#include <cuda_runtime.h>
#include <cuda_bf16.h>
#include <cstdint>
#include <math.h>

#define NB 32
#define NN 512
#define DD 256
#define INV_EPS 10.0f
#define TINYF 1e-16f
#define MARG (1.0f/512.0f)
#define ITERS 15
#define PGRID 128      // 32 clusters x 4 CTAs; 1 block/SM
#define PTHREADS 512

// ---------------- scratch (static __device__; no allocations) ----------------
static __device__ float g_rx[NB*NN];                     // 1/|x_row|
static __device__ float g_ry[NB*NN];                     // 1/|y_row|
static __device__ float g_E [(size_t)NB*NN*NN];          // 32 MB  E = exp(-C/eps) fp32
static __device__ float g_cpart[PGRID];                  // per-block cost partials

// ---------------- 1) reciprocal row norms of x and y --------------------------
__global__ void norm_kernel(const float* __restrict__ x, const float* __restrict__ y) {
    int gw   = (blockIdx.x * blockDim.x + threadIdx.x) >> 5;
    int lane = threadIdx.x & 31;
    const float* src; float* dst; int row;
    if (gw < NB*NN) { src = x; dst = g_rx; row = gw; }
    else            { src = y; dst = g_ry; row = gw - NB*NN; }
    const float4* s4 = (const float4*)(src + (size_t)row * DD);
    float4 a = s4[lane];
    float4 b = s4[lane + 32];
    float ss = a.x*a.x + a.y*a.y + a.z*a.z + a.w*a.w
             + b.x*b.x + b.y*b.y + b.z*b.z + b.w*b.w;
    #pragma unroll
    for (int o = 16; o; o >>= 1) ss += __shfl_xor_sync(0xffffffffu, ss, o);
    if (lane == 0) dst[row] = rsqrtf(ss);   // norms ~16; 1e-8 clamp never binds
}

// ---------------- 2) tf32 tensor-core GEMM: C = 1 - (x/|x|)(y/|y|)^T ---------
__device__ __forceinline__ unsigned f2tf32(float f) {
    unsigned r;
    asm("cvt.rna.tf32.f32 %0, %1;" : "=r"(r) : "f"(f));
    return r;
}

__global__ void __launch_bounds__(256) gemm_kernel(float* __restrict__ Cout,
                                                   const float* __restrict__ x,
                                                   const float* __restrict__ y) {
    __shared__ float As[128][36];
    __shared__ float Bs[64][36];
    int b  = blockIdx.z;
    int m0 = blockIdx.y * 128, n0 = blockIdx.x * 64;
    const float* A = x + (size_t)b * NN * DD;
    const float* B = y + (size_t)b * NN * DD;
    int t = threadIdx.x, lane = t & 31, warp = t >> 5;
    int wm = (warp >> 1) * 32;
    int wn = (warp & 1) * 32;
    int lr = t >> 3;
    int lc = (t & 7) * 4;

    float ra[4], rb[2];
    #pragma unroll
    for (int i = 0; i < 4; i++) ra[i] = g_rx[b*NN + m0 + lr + 32*i];
    #pragma unroll
    for (int i = 0; i < 2; i++) rb[i] = g_ry[b*NN + n0 + lr + 32*i];

    float acc[2][4][4];
    #pragma unroll
    for (int i=0;i<2;i++)
        #pragma unroll
        for (int j=0;j<4;j++)
            #pragma unroll
            for (int k=0;k<4;k++) acc[i][j][k] = 0.f;

    for (int k0 = 0; k0 < DD; k0 += 32) {
        #pragma unroll
        for (int i = 0; i < 4; i++) {
            float4 v = *(const float4*)(A + (size_t)(m0 + lr + 32*i) * DD + k0 + lc);
            float4 w;
            w.x = __uint_as_float(f2tf32(v.x * ra[i])); w.y = __uint_as_float(f2tf32(v.y * ra[i]));
            w.z = __uint_as_float(f2tf32(v.z * ra[i])); w.w = __uint_as_float(f2tf32(v.w * ra[i]));
            *(float4*)&As[lr + 32*i][lc] = w;
        }
        #pragma unroll
        for (int i = 0; i < 2; i++) {
            float4 v = *(const float4*)(B + (size_t)(n0 + lr + 32*i) * DD + k0 + lc);
            float4 w;
            w.x = __uint_as_float(f2tf32(v.x * rb[i])); w.y = __uint_as_float(f2tf32(v.y * rb[i]));
            w.z = __uint_as_float(f2tf32(v.z * rb[i])); w.w = __uint_as_float(f2tf32(v.w * rb[i]));
            *(float4*)&Bs[lr + 32*i][lc] = w;
        }
        __syncthreads();
        #pragma unroll
        for (int s = 0; s < 4; s++) {
            int kc = s * 8 + (lane & 3);
            unsigned bf[4][2];
            #pragma unroll
            for (int nt = 0; nt < 4; nt++) {
                int nb = wn + nt*8 + (lane >> 2);
                bf[nt][0] = __float_as_uint(Bs[nb][kc]);
                bf[nt][1] = __float_as_uint(Bs[nb][kc + 4]);
            }
            #pragma unroll
            for (int mt = 0; mt < 2; mt++) {
                int ma = wm + mt*16 + (lane >> 2);
                unsigned a0 = __float_as_uint(As[ma    ][kc]);
                unsigned a1 = __float_as_uint(As[ma + 8][kc]);
                unsigned a2 = __float_as_uint(As[ma    ][kc + 4]);
                unsigned a3 = __float_as_uint(As[ma + 8][kc + 4]);
                #pragma unroll
                for (int nt = 0; nt < 4; nt++) {
                    asm volatile(
                        "mma.sync.aligned.m16n8k8.row.col.f32.tf32.tf32.f32 "
                        "{%0,%1,%2,%3}, {%4,%5,%6,%7}, {%8,%9}, {%0,%1,%2,%3};"
                        : "+f"(acc[mt][nt][0]), "+f"(acc[mt][nt][1]),
                          "+f"(acc[mt][nt][2]), "+f"(acc[mt][nt][3])
                        : "r"(a0), "r"(a1), "r"(a2), "r"(a3),
                          "r"(bf[nt][0]), "r"(bf[nt][1]));
                }
            }
        }
        __syncthreads();
    }

    size_t base = (size_t)b * NN * NN;
    #pragma unroll
    for (int mt = 0; mt < 2; mt++) {
        #pragma unroll
        for (int nt = 0; nt < 4; nt++) {
            int m = m0 + wm + mt*16 + (lane >> 2);
            int n = n0 + wn + nt*8 + (lane & 3)*2;
            float c0 = 1.0f - acc[mt][nt][0];
            float c1 = 1.0f - acc[mt][nt][1];
            float c2 = 1.0f - acc[mt][nt][2];
            float c3 = 1.0f - acc[mt][nt][3];
            *(float2*)&Cout[base + (size_t)m*NN + n]     = make_float2(c0, c1);
            *(float2*)&g_E [base + (size_t)m*NN + n]     = make_float2(__expf(-INV_EPS*c0), __expf(-INV_EPS*c1));
            *(float2*)&Cout[base + (size_t)(m+8)*NN + n] = make_float2(c2, c3);
            *(float2*)&g_E [base + (size_t)(m+8)*NN + n] = make_float2(__expf(-INV_EPS*c2), __expf(-INV_EPS*c3));
        }
    }
}

// ---------------- 3) persistent Sinkhorn kernel (cluster of 4) ---------------
// 32 clusters x 4 CTAs; CTA rank r handles rows [r*128, +128) of batch
// b = blockIdx.x/4.  E tile in smem as bf16 (128KB).  Per-iteration cross-CTA
// column-partial exchange via DSMEM after one cluster barrier (double-buffered).
#define SM_E     0
#define SM_COLP  131072                       // 16 warps x 512 floats = 32768
#define SM_COLR  (SM_COLP + 32768)            // 2 x 512 floats (double buffer)
#define SM_W     (SM_COLR + 4096)
#define SM_Q     (SM_W + 2048)
#define SM_P     (SM_Q + 2048)
#define SM_SU    (SM_P + 512)
#define SM_CRED  (SM_SU + 512)
#define SM_TOT   (SM_CRED + 64 + 64)

__device__ __forceinline__ unsigned smem_u32(const void* p) {
    unsigned a;
    asm("{ .reg .u64 t; cvta.to.shared.u64 t, %1; cvt.u32.u64 %0, t; }"
        : "=r"(a) : "l"(p));
    return a;
}
__device__ __forceinline__ float dsmem_ld(unsigned local_addr, unsigned rank) {
    unsigned rem; float v;
    asm volatile("mapa.shared::cluster.u32 %0, %1, %2;" : "=r"(rem)
                 : "r"(local_addr), "r"(rank));
    asm volatile("ld.shared::cluster.f32 %0, [%1];" : "=f"(v) : "r"(rem));
    return v;
}

__global__ void __cluster_dims__(4, 1, 1) __launch_bounds__(PTHREADS, 1)
sink_kernel(float* __restrict__ pi, const float* __restrict__ C) {
    extern __shared__ unsigned char sm[];
    unsigned* Eu  = (unsigned*)(sm + SM_E);      // [128][256] words (2 bf16/word)
    float* colp   = (float*)(sm + SM_COLP);      // [16][512]
    float* colr   = (float*)(sm + SM_COLR);      // [2][512]
    float* w      = (float*)(sm + SM_W);         // [512]
    float* q      = (float*)(sm + SM_Q);         // [512]
    float* p      = (float*)(sm + SM_P);         // [128]
    float* su     = (float*)(sm + SM_SU);        // [128]
    float* cred   = (float*)(sm + SM_CRED);      // [16]

    int g = blockIdx.x, b = g >> 2;
    unsigned rank;
    asm("mov.u32 %0, %%cluster_ctarank;" : "=r"(rank));
    int row0 = (int)rank * 128;
    int t = threadIdx.x, warp = t >> 5, lane = t & 31;
    unsigned sb = smem_u32(sm);
    const float* Eg = g_E + ((size_t)b * NN + row0) * NN;

    // prologue: fp32 E -> bf16 smem
    for (int i = t; i < 128*512/4; i += PTHREADS) {
        float4 v = *(const float4*)(Eg + (size_t)i * 4);
        __nv_bfloat162 lo = __floats2bfloat162_rn(v.x, v.y);
        __nv_bfloat162 hi = __floats2bfloat162_rn(v.z, v.w);
        uint2 pk;
        pk.x = *(unsigned*)&lo;
        pk.y = *(unsigned*)&hi;
        *(uint2*)&Eu[i*2] = pk;
    }
    if (t < 512) { w[t] = 1.f; q[t] = 1.f; }
    if (t < 128) p[t] = 1.f;
    __syncthreads();

    for (int it = 0; it < ITERS; it++) {
        // lane owns column pairs {2*lane + 64k, 2*lane+64k+1}, k=0..7
        float wreg[16];
        #pragma unroll
        for (int k = 0; k < 8; k++) {
            float2 wp = *(const float2*)&w[2*lane + 64*k];
            wreg[2*k] = wp.x; wreg[2*k+1] = wp.y;
        }
        float colacc[16];
        #pragma unroll
        for (int i = 0; i < 16; i++) colacc[i] = 0.f;

        // 8 rows per warp, processed in pairs (dual shuffle chains)
        #pragma unroll
        for (int rg = 0; rg < 4; rg++) {
            int rowA = warp * 8 + rg * 2;
            int rowB = rowA + 1;
            const unsigned* EA = &Eu[rowA * 256];
            const unsigned* EB = &Eu[rowB * 256];
            unsigned ea[8], eb[8];
            #pragma unroll
            for (int k = 0; k < 8; k++) ea[k] = EA[lane + 32*k];
            #pragma unroll
            for (int k = 0; k < 8; k++) eb[k] = EB[lane + 32*k];

            float dA0=0.f, dA1=0.f, dB0=0.f, dB1=0.f;
            #pragma unroll
            for (int k = 0; k < 8; k++) {
                dA0 += __uint_as_float(ea[k] << 16)         * wreg[2*k];
                dA1 += __uint_as_float(ea[k] & 0xffff0000u) * wreg[2*k+1];
                dB0 += __uint_as_float(eb[k] << 16)         * wreg[2*k];
                dB1 += __uint_as_float(eb[k] & 0xffff0000u) * wreg[2*k+1];
            }
            float dA = dA0 + dA1, dB = dB0 + dB1;
            #pragma unroll
            for (int o = 16; o; o >>= 1) {
                dA += __shfl_xor_sync(0xffffffffu, dA, o);
                dB += __shfl_xor_sync(0xffffffffu, dB, o);
            }
            float pA = p[rowA], pB = p[rowB];
            float uA = MARG / (pA * dA + TINYF);
            float uB = MARG / (pB * dB + TINYF);
            float pnA = pA * uA, pnB = pB * uB;
            if (lane == 0) {
                p[rowA] = pnA; p[rowB] = pnB;
                if (it == ITERS - 1) { su[rowA] = uA * pnA; su[rowB] = uB * pnB; }
            }
            #pragma unroll
            for (int k = 0; k < 8; k++) {
                colacc[2*k]   += __uint_as_float(ea[k] << 16)         * pnA
                               + __uint_as_float(eb[k] << 16)         * pnB;
                colacc[2*k+1] += __uint_as_float(ea[k] & 0xffff0000u) * pnA
                               + __uint_as_float(eb[k] & 0xffff0000u) * pnB;
            }
        }
        // stage per-warp column partials
        #pragma unroll
        for (int k = 0; k < 8; k++)
            *(float2*)&colp[warp * 512 + 2*lane + 64*k] =
                make_float2(colacc[2*k], colacc[2*k+1]);
        __syncthreads();
        // block column reduce -> colr[it&1]
        if (t < 512) {
            float s = 0.f;
            #pragma unroll
            for (int j = 0; j < 16; j++) s += colp[j * 512 + t];
            colr[(it & 1) * 512 + t] = s;
        }
        // one cluster barrier: partials visible cluster-wide
        asm volatile("barrier.cluster.arrive.aligned;" ::: "memory");
        asm volatile("barrier.cluster.wait.aligned;"   ::: "memory");
        // column update via DSMEM (deterministic rank order, redundant per CTA)
        if (t < 512) {
            unsigned addr = sb + SM_COLR + (unsigned)(it & 1) * 2048 + t * 4;
            float s0 = dsmem_ld(addr, 0);
            float s1 = dsmem_ld(addr, 1);
            float s2 = dsmem_ld(addr, 2);
            float s3 = dsmem_ld(addr, 3);
            float tot = (s0 + s1) + (s2 + s3);
            float qold = q[t];
            float v = MARG / (qold * tot + TINYF);
            float qn = qold * v;
            q[t] = qn;
            w[t] = qn * v;      // w = v*q
        }
        __syncthreads();
    }

    // final: pi = Efp32 * su[row] * w[col]; cost partial
    size_t base = ((size_t)b * NN + row0) * NN;
    float csum = 0.f;
    for (int r = 0; r < 8; r++) {
        int row = warp * 8 + r;
        float s_u = su[row];
        const float4* E4 = (const float4*)(g_E + base + (size_t)row * NN);
        const float4* C4 = (const float4*)(C   + base + (size_t)row * NN);
        float4*       P4 = (float4*)      (pi  + base + (size_t)row * NN);
        #pragma unroll
        for (int k = 0; k < 4; k++) {
            int idx = lane + 32*k;
            float4 e  = E4[idx];
            float4 cc = C4[idx];
            int c0 = idx * 4;
            float4 pv;
            pv.x = e.x * s_u * w[c0+0];
            pv.y = e.y * s_u * w[c0+1];
            pv.z = e.z * s_u * w[c0+2];
            pv.w = e.w * s_u * w[c0+3];
            csum += pv.x*cc.x + pv.y*cc.y + pv.z*cc.z + pv.w*cc.w;
            P4[idx] = pv;
        }
    }
    #pragma unroll
    for (int o = 16; o; o >>= 1) csum += __shfl_xor_sync(0xffffffffu, csum, o);
    if (lane == 0) cred[warp] = csum;
    __syncthreads();
    if (t == 0) {
        float s = 0.f;
        #pragma unroll
        for (int i = 0; i < 16; i++) s += cred[i];
        g_cpart[g] = s;
    }
    // cluster exit barrier: no CTA may leave while siblings still read its smem
    asm volatile("barrier.cluster.arrive.aligned;" ::: "memory");
    asm volatile("barrier.cluster.wait.aligned;"   ::: "memory");
}

// ---------------- 4) reduce cost partials ------------------------------------
__global__ void cost_kernel(float* __restrict__ cost) {
    int b = threadIdx.x;
    if (b < NB) {
        float s = 0.f;
        #pragma unroll
        for (int k = 0; k < 4; k++) s += g_cpart[b*4 + k];
        cost[b] = s;
    }
}

// ---------------- launch ------------------------------------------------------
extern "C" void kernel_launch(void* const* d_in, const int* in_sizes, int n_in,
                              void* d_out, int out_size) {
    const float* x = (const float*)d_in[0];
    const float* y = (const float*)d_in[1];
    float* out  = (float*)d_out;
    float* cost = out;
    float* pi   = out + NB;
    float* C    = out + NB + (size_t)NB * NN * NN;

    static int smem_set = 0;
    if (!smem_set) {
        cudaFuncSetAttribute(sink_kernel,
                             cudaFuncAttributeMaxDynamicSharedMemorySize, SM_TOT);
        smem_set = 1;
    }

    norm_kernel<<<4096, 256>>>(x, y);
    gemm_kernel<<<dim3(8, 4, NB), 256>>>(C, x, y);
    sink_kernel<<<PGRID, PTHREADS, SM_TOT>>>(pi, C);
    cost_kernel<<<1, 32>>>(cost);
}

// round 9
// speedup vs baseline: 1.5289x; 1.0545x over previous
#include <cuda_runtime.h>
#include <cuda_bf16.h>
#include <cstdint>
#include <math.h>

#define NB 32
#define NN 512
#define DD 256
#define INV_EPS 10.0f
#define TINYF 1e-16f
#define MARG (1.0f/512.0f)
#define ITERS 15
#define PGRID 128      // 32 clusters x 4 CTAs; 1 block/SM
#define PTHREADS 512

// ---------------- scratch (static __device__; no allocations) ----------------
static __device__ float g_E [(size_t)NB*NN*NN];          // 32 MB  E = exp(-C/eps) fp32

// ---------------- 1) tf32 tensor-core GEMM on RAW x,y; epilogue normalizes ---
// C = 1 - (x.y) / (|x||y|);  E = exp(-10C).  Row norms computed during staging.
__device__ __forceinline__ unsigned f2tf32(float f) {
    unsigned r;
    asm("cvt.rna.tf32.f32 %0, %1;" : "=r"(r) : "f"(f));
    return r;
}

__global__ void __launch_bounds__(256) gemm_kernel(float* __restrict__ Cout,
                                                   const float* __restrict__ x,
                                                   const float* __restrict__ y) {
    __shared__ float As[128][36];
    __shared__ float Bs[64][36];
    __shared__ float ran[128];
    __shared__ float rbn[64];
    int b  = blockIdx.z;
    int m0 = blockIdx.y * 128, n0 = blockIdx.x * 64;
    const float* A = x + (size_t)b * NN * DD;
    const float* B = y + (size_t)b * NN * DD;
    int t = threadIdx.x, lane = t & 31, warp = t >> 5;
    int wm = (warp >> 1) * 32;
    int wn = (warp & 1) * 32;
    int lr = t >> 3;                // 0..31  (row within 32-row slab)
    int lc = (t & 7) * 4;           // 0..28  (column chunk)

    float ssA[4] = {0,0,0,0};
    float ssB[2] = {0,0};

    float acc[2][4][4];
    #pragma unroll
    for (int i=0;i<2;i++)
        #pragma unroll
        for (int j=0;j<4;j++)
            #pragma unroll
            for (int k=0;k<4;k++) acc[i][j][k] = 0.f;

    for (int k0 = 0; k0 < DD; k0 += 32) {
        #pragma unroll
        for (int i = 0; i < 4; i++) {
            float4 v = *(const float4*)(A + (size_t)(m0 + lr + 32*i) * DD + k0 + lc);
            ssA[i] += v.x*v.x + v.y*v.y + v.z*v.z + v.w*v.w;
            float4 w;
            w.x = __uint_as_float(f2tf32(v.x)); w.y = __uint_as_float(f2tf32(v.y));
            w.z = __uint_as_float(f2tf32(v.z)); w.w = __uint_as_float(f2tf32(v.w));
            *(float4*)&As[lr + 32*i][lc] = w;
        }
        #pragma unroll
        for (int i = 0; i < 2; i++) {
            float4 v = *(const float4*)(B + (size_t)(n0 + lr + 32*i) * DD + k0 + lc);
            ssB[i] += v.x*v.x + v.y*v.y + v.z*v.z + v.w*v.w;
            float4 w;
            w.x = __uint_as_float(f2tf32(v.x)); w.y = __uint_as_float(f2tf32(v.y));
            w.z = __uint_as_float(f2tf32(v.z)); w.w = __uint_as_float(f2tf32(v.w));
            *(float4*)&Bs[lr + 32*i][lc] = w;
        }
        __syncthreads();
        #pragma unroll
        for (int s = 0; s < 4; s++) {
            int kc = s * 8 + (lane & 3);
            unsigned bf[4][2];
            #pragma unroll
            for (int nt = 0; nt < 4; nt++) {
                int nb = wn + nt*8 + (lane >> 2);
                bf[nt][0] = __float_as_uint(Bs[nb][kc]);
                bf[nt][1] = __float_as_uint(Bs[nb][kc + 4]);
            }
            #pragma unroll
            for (int mt = 0; mt < 2; mt++) {
                int ma = wm + mt*16 + (lane >> 2);
                unsigned a0 = __float_as_uint(As[ma    ][kc]);
                unsigned a1 = __float_as_uint(As[ma + 8][kc]);
                unsigned a2 = __float_as_uint(As[ma    ][kc + 4]);
                unsigned a3 = __float_as_uint(As[ma + 8][kc + 4]);
                #pragma unroll
                for (int nt = 0; nt < 4; nt++) {
                    asm volatile(
                        "mma.sync.aligned.m16n8k8.row.col.f32.tf32.tf32.f32 "
                        "{%0,%1,%2,%3}, {%4,%5,%6,%7}, {%8,%9}, {%0,%1,%2,%3};"
                        : "+f"(acc[mt][nt][0]), "+f"(acc[mt][nt][1]),
                          "+f"(acc[mt][nt][2]), "+f"(acc[mt][nt][3])
                        : "r"(a0), "r"(a1), "r"(a2), "r"(a3),
                          "r"(bf[nt][0]), "r"(bf[nt][1]));
                }
            }
        }
        __syncthreads();
    }

    // reduce sum-of-squares across the 8 staging threads of each row
    #pragma unroll
    for (int o = 4; o; o >>= 1) {
        #pragma unroll
        for (int i = 0; i < 4; i++) ssA[i] += __shfl_xor_sync(0xffffffffu, ssA[i], o);
        #pragma unroll
        for (int i = 0; i < 2; i++) ssB[i] += __shfl_xor_sync(0xffffffffu, ssB[i], o);
    }
    if ((t & 7) == 0) {
        #pragma unroll
        for (int i = 0; i < 4; i++) ran[lr + 32*i] = rsqrtf(ssA[i]);
        #pragma unroll
        for (int i = 0; i < 2; i++) rbn[lr + 32*i] = rsqrtf(ssB[i]);
    }
    __syncthreads();

    size_t base = (size_t)b * NN * NN;
    #pragma unroll
    for (int mt = 0; mt < 2; mt++) {
        #pragma unroll
        for (int nt = 0; nt < 4; nt++) {
            int ml = wm + mt*16 + (lane >> 2);
            int nl = wn + nt*8 + (lane & 3)*2;
            int m = m0 + ml, n = n0 + nl;
            float r0 = ran[ml];
            float r2 = ran[ml + 8];
            float rb0 = rbn[nl], rb1 = rbn[nl + 1];
            float c0 = 1.0f - acc[mt][nt][0] * r0 * rb0;
            float c1 = 1.0f - acc[mt][nt][1] * r0 * rb1;
            float c2 = 1.0f - acc[mt][nt][2] * r2 * rb0;
            float c3 = 1.0f - acc[mt][nt][3] * r2 * rb1;
            *(float2*)&Cout[base + (size_t)m*NN + n]     = make_float2(c0, c1);
            *(float2*)&g_E [base + (size_t)m*NN + n]     = make_float2(__expf(-INV_EPS*c0), __expf(-INV_EPS*c1));
            *(float2*)&Cout[base + (size_t)(m+8)*NN + n] = make_float2(c2, c3);
            *(float2*)&g_E [base + (size_t)(m+8)*NN + n] = make_float2(__expf(-INV_EPS*c2), __expf(-INV_EPS*c3));
        }
    }
}

// ---------------- 2) persistent Sinkhorn kernel (cluster of 4) ---------------
#define SM_E     0
#define SM_COLP  131072                       // 16 warps x 512 floats = 32768
#define SM_COLR  (SM_COLP + 32768)            // 2 x 512 floats (double buffer)
#define SM_W     (SM_COLR + 4096)
#define SM_Q     (SM_W + 2048)
#define SM_P     (SM_Q + 2048)
#define SM_SU    (SM_P + 512)
#define SM_CRED  (SM_SU + 512)
#define SM_TOT   (SM_CRED + 64 + 64)

__device__ __forceinline__ unsigned smem_u32(const void* p) {
    unsigned a;
    asm("{ .reg .u64 t; cvta.to.shared.u64 t, %1; cvt.u32.u64 %0, t; }"
        : "=r"(a) : "l"(p));
    return a;
}
__device__ __forceinline__ float dsmem_ld(unsigned local_addr, unsigned rank) {
    unsigned rem; float v;
    asm volatile("mapa.shared::cluster.u32 %0, %1, %2;" : "=r"(rem)
                 : "r"(local_addr), "r"(rank));
    asm volatile("ld.shared::cluster.f32 %0, [%1];" : "=f"(v) : "r"(rem));
    return v;
}

__global__ void __cluster_dims__(4, 1, 1) __launch_bounds__(PTHREADS, 1)
sink_kernel(float* __restrict__ cost, float* __restrict__ pi,
            const float* __restrict__ C) {
    extern __shared__ unsigned char sm[];
    unsigned* Eu  = (unsigned*)(sm + SM_E);      // [128][256] words (2 bf16/word)
    float* colp   = (float*)(sm + SM_COLP);      // [16][512]
    float* colr   = (float*)(sm + SM_COLR);      // [2][512]
    float* w      = (float*)(sm + SM_W);         // [512]
    float* q      = (float*)(sm + SM_Q);         // [512]
    float* p      = (float*)(sm + SM_P);         // [128]
    float* su     = (float*)(sm + SM_SU);        // [128]
    float* cred   = (float*)(sm + SM_CRED);      // [16]

    int g = blockIdx.x, b = g >> 2;
    unsigned rank;
    asm("mov.u32 %0, %%cluster_ctarank;" : "=r"(rank));
    int row0 = (int)rank * 128;
    int t = threadIdx.x, warp = t >> 5, lane = t & 31;
    unsigned sb = smem_u32(sm);
    const float* Eg = g_E + ((size_t)b * NN + row0) * NN;

    // prologue: fp32 E -> bf16 smem
    for (int i = t; i < 128*512/4; i += PTHREADS) {
        float4 v = *(const float4*)(Eg + (size_t)i * 4);
        __nv_bfloat162 lo = __floats2bfloat162_rn(v.x, v.y);
        __nv_bfloat162 hi = __floats2bfloat162_rn(v.z, v.w);
        uint2 pk;
        pk.x = *(unsigned*)&lo;
        pk.y = *(unsigned*)&hi;
        *(uint2*)&Eu[i*2] = pk;
    }
    if (t < 512) { w[t] = 1.f; q[t] = 1.f; }
    if (t < 128) p[t] = 1.f;
    __syncthreads();

    for (int it = 0; it < ITERS; it++) {
        // lane owns column pairs {2*lane + 64k, 2*lane+64k+1}, k=0..7
        float wreg[16];
        #pragma unroll
        for (int k = 0; k < 8; k++) {
            float2 wp = *(const float2*)&w[2*lane + 64*k];
            wreg[2*k] = wp.x; wreg[2*k+1] = wp.y;
        }
        float colacc[16];
        #pragma unroll
        for (int i = 0; i < 16; i++) colacc[i] = 0.f;

        // 8 rows per warp, processed in pairs (dual shuffle chains)
        #pragma unroll
        for (int rg = 0; rg < 4; rg++) {
            int rowA = warp * 8 + rg * 2;
            int rowB = rowA + 1;
            const unsigned* EA = &Eu[rowA * 256];
            const unsigned* EB = &Eu[rowB * 256];
            unsigned ea[8], eb[8];
            #pragma unroll
            for (int k = 0; k < 8; k++) ea[k] = EA[lane + 32*k];
            #pragma unroll
            for (int k = 0; k < 8; k++) eb[k] = EB[lane + 32*k];

            float dA0=0.f, dA1=0.f, dB0=0.f, dB1=0.f;
            #pragma unroll
            for (int k = 0; k < 8; k++) {
                dA0 += __uint_as_float(ea[k] << 16)         * wreg[2*k];
                dA1 += __uint_as_float(ea[k] & 0xffff0000u) * wreg[2*k+1];
                dB0 += __uint_as_float(eb[k] << 16)         * wreg[2*k];
                dB1 += __uint_as_float(eb[k] & 0xffff0000u) * wreg[2*k+1];
            }
            float dA = dA0 + dA1, dB = dB0 + dB1;
            #pragma unroll
            for (int o = 16; o; o >>= 1) {
                dA += __shfl_xor_sync(0xffffffffu, dA, o);
                dB += __shfl_xor_sync(0xffffffffu, dB, o);
            }
            float pA = p[rowA], pB = p[rowB];
            float uA = MARG / (pA * dA + TINYF);
            float uB = MARG / (pB * dB + TINYF);
            float pnA = pA * uA, pnB = pB * uB;
            if (lane == 0) {
                p[rowA] = pnA; p[rowB] = pnB;
                if (it == ITERS - 1) { su[rowA] = uA * pnA; su[rowB] = uB * pnB; }
            }
            #pragma unroll
            for (int k = 0; k < 8; k++) {
                colacc[2*k]   += __uint_as_float(ea[k] << 16)         * pnA
                               + __uint_as_float(eb[k] << 16)         * pnB;
                colacc[2*k+1] += __uint_as_float(ea[k] & 0xffff0000u) * pnA
                               + __uint_as_float(eb[k] & 0xffff0000u) * pnB;
            }
        }
        // stage per-warp column partials
        #pragma unroll
        for (int k = 0; k < 8; k++)
            *(float2*)&colp[warp * 512 + 2*lane + 64*k] =
                make_float2(colacc[2*k], colacc[2*k+1]);
        __syncthreads();
        // block column reduce -> colr[it&1]
        if (t < 512) {
            float s = 0.f;
            #pragma unroll
            for (int j = 0; j < 16; j++) s += colp[j * 512 + t];
            colr[(it & 1) * 512 + t] = s;
        }
        // one cluster barrier: partials visible cluster-wide
        asm volatile("barrier.cluster.arrive.aligned;" ::: "memory");
        asm volatile("barrier.cluster.wait.aligned;"   ::: "memory");
        // column update via DSMEM (deterministic rank order, redundant per CTA)
        if (t < 512) {
            unsigned addr = sb + SM_COLR + (unsigned)(it & 1) * 2048 + t * 4;
            float s0 = dsmem_ld(addr, 0);
            float s1 = dsmem_ld(addr, 1);
            float s2 = dsmem_ld(addr, 2);
            float s3 = dsmem_ld(addr, 3);
            float tot = (s0 + s1) + (s2 + s3);
            float qold = q[t];
            float v = MARG / (qold * tot + TINYF);
            float qn = qold * v;
            q[t] = qn;
            w[t] = qn * v;      // w = v*q
        }
        __syncthreads();
    }

    // final: pi = Efp32 * su[row] * w[col]; cost partial
    size_t base = ((size_t)b * NN + row0) * NN;
    float csum = 0.f;
    for (int r = 0; r < 8; r++) {
        int row = warp * 8 + r;
        float s_u = su[row];
        const float4* E4 = (const float4*)(g_E + base + (size_t)row * NN);
        const float4* C4 = (const float4*)(C   + base + (size_t)row * NN);
        float4*       P4 = (float4*)      (pi  + base + (size_t)row * NN);
        #pragma unroll
        for (int k = 0; k < 4; k++) {
            int idx = lane + 32*k;
            float4 e  = E4[idx];
            float4 cc = C4[idx];
            int c0 = idx * 4;
            float4 pv;
            pv.x = e.x * s_u * w[c0+0];
            pv.y = e.y * s_u * w[c0+1];
            pv.z = e.z * s_u * w[c0+2];
            pv.w = e.w * s_u * w[c0+3];
            csum += pv.x*cc.x + pv.y*cc.y + pv.z*cc.z + pv.w*cc.w;
            P4[idx] = pv;
        }
    }
    #pragma unroll
    for (int o = 16; o; o >>= 1) csum += __shfl_xor_sync(0xffffffffu, csum, o);
    if (lane == 0) cred[warp] = csum;
    __syncthreads();
    if (t == 0) {
        float s = 0.f;
        #pragma unroll
        for (int i = 0; i < 16; i++) s += cred[i];
        cred[0] = s;                 // per-CTA cost partial, staged for DSMEM
    }
    // cluster barrier: cred[0] visible cluster-wide; also protects smem from
    // early exit while siblings still read it
    asm volatile("barrier.cluster.arrive.aligned;" ::: "memory");
    asm volatile("barrier.cluster.wait.aligned;"   ::: "memory");
    if (rank == 0 && t == 0) {
        unsigned addr = sb + SM_CRED;
        float s0 = dsmem_ld(addr, 0);
        float s1 = dsmem_ld(addr, 1);
        float s2 = dsmem_ld(addr, 2);
        float s3 = dsmem_ld(addr, 3);
        cost[b] = (s0 + s1) + (s2 + s3);
    }
    asm volatile("barrier.cluster.arrive.aligned;" ::: "memory");
    asm volatile("barrier.cluster.wait.aligned;"   ::: "memory");
}

// ---------------- launch ------------------------------------------------------
extern "C" void kernel_launch(void* const* d_in, const int* in_sizes, int n_in,
                              void* d_out, int out_size) {
    const float* x = (const float*)d_in[0];
    const float* y = (const float*)d_in[1];
    float* out  = (float*)d_out;
    float* cost = out;
    float* pi   = out + NB;
    float* C    = out + NB + (size_t)NB * NN * NN;

    static int smem_set = 0;
    if (!smem_set) {
        cudaFuncSetAttribute(sink_kernel,
                             cudaFuncAttributeMaxDynamicSharedMemorySize, SM_TOT);
        smem_set = 1;
    }

    gemm_kernel<<<dim3(8, 4, NB), 256>>>(C, x, y);
    sink_kernel<<<PGRID, PTHREADS, SM_TOT>>>(cost, pi, C);
}

// round 11
// speedup vs baseline: 1.5734x; 1.0291x over previous
#include <cuda_runtime.h>
#include <cuda_bf16.h>
#include <cstdint>
#include <math.h>

#define NB 32
#define NN 512
#define DD 256
#define INV_EPS 10.0f
#define TINYF 1e-16f
#define MARG (1.0f/512.0f)
#define ITERS 15
#define PGRID 128      // 32 clusters x 4 CTAs; 1 block/SM
#define PTHREADS 512

// ---------------- scratch (static __device__; no allocations) ----------------
static __device__ unsigned g_Ebf[(size_t)NB*NN*NN/2];    // 16 MB E as packed bf16x2

// ---------------- 1) tf32 tensor-core GEMM on RAW x,y; epilogue normalizes ---
// C = 1 - (x.y)/(|x||y|);  E = bf16(exp(-10C)).  Row norms computed in staging.
__device__ __forceinline__ unsigned f2tf32(float f) {
    unsigned r;
    asm("cvt.rna.tf32.f32 %0, %1;" : "=r"(r) : "f"(f));
    return r;
}

__global__ void __launch_bounds__(256) gemm_kernel(float* __restrict__ Cout,
                                                   const float* __restrict__ x,
                                                   const float* __restrict__ y) {
    __shared__ float As[128][36];
    __shared__ float Bs[64][36];
    __shared__ float ran[128];
    __shared__ float rbn[64];
    int b  = blockIdx.z;
    int m0 = blockIdx.y * 128, n0 = blockIdx.x * 64;
    const float* A = x + (size_t)b * NN * DD;
    const float* B = y + (size_t)b * NN * DD;
    int t = threadIdx.x, lane = t & 31, warp = t >> 5;
    int wm = (warp >> 1) * 32;
    int wn = (warp & 1) * 32;
    int lr = t >> 3;                // 0..31  (row within 32-row slab)
    int lc = (t & 7) * 4;           // 0..28  (column chunk)

    float ssA[4] = {0,0,0,0};
    float ssB[2] = {0,0};

    float acc[2][4][4];
    #pragma unroll
    for (int i=0;i<2;i++)
        #pragma unroll
        for (int j=0;j<4;j++)
            #pragma unroll
            for (int k=0;k<4;k++) acc[i][j][k] = 0.f;

    for (int k0 = 0; k0 < DD; k0 += 32) {
        #pragma unroll
        for (int i = 0; i < 4; i++) {
            float4 v = *(const float4*)(A + (size_t)(m0 + lr + 32*i) * DD + k0 + lc);
            ssA[i] += v.x*v.x + v.y*v.y + v.z*v.z + v.w*v.w;
            float4 w;
            w.x = __uint_as_float(f2tf32(v.x)); w.y = __uint_as_float(f2tf32(v.y));
            w.z = __uint_as_float(f2tf32(v.z)); w.w = __uint_as_float(f2tf32(v.w));
            *(float4*)&As[lr + 32*i][lc] = w;
        }
        #pragma unroll
        for (int i = 0; i < 2; i++) {
            float4 v = *(const float4*)(B + (size_t)(n0 + lr + 32*i) * DD + k0 + lc);
            ssB[i] += v.x*v.x + v.y*v.y + v.z*v.z + v.w*v.w;
            float4 w;
            w.x = __uint_as_float(f2tf32(v.x)); w.y = __uint_as_float(f2tf32(v.y));
            w.z = __uint_as_float(f2tf32(v.z)); w.w = __uint_as_float(f2tf32(v.w));
            *(float4*)&Bs[lr + 32*i][lc] = w;
        }
        __syncthreads();
        #pragma unroll
        for (int s = 0; s < 4; s++) {
            int kc = s * 8 + (lane & 3);
            unsigned bf[4][2];
            #pragma unroll
            for (int nt = 0; nt < 4; nt++) {
                int nb = wn + nt*8 + (lane >> 2);
                bf[nt][0] = __float_as_uint(Bs[nb][kc]);
                bf[nt][1] = __float_as_uint(Bs[nb][kc + 4]);
            }
            #pragma unroll
            for (int mt = 0; mt < 2; mt++) {
                int ma = wm + mt*16 + (lane >> 2);
                unsigned a0 = __float_as_uint(As[ma    ][kc]);
                unsigned a1 = __float_as_uint(As[ma + 8][kc]);
                unsigned a2 = __float_as_uint(As[ma    ][kc + 4]);
                unsigned a3 = __float_as_uint(As[ma + 8][kc + 4]);
                #pragma unroll
                for (int nt = 0; nt < 4; nt++) {
                    asm volatile(
                        "mma.sync.aligned.m16n8k8.row.col.f32.tf32.tf32.f32 "
                        "{%0,%1,%2,%3}, {%4,%5,%6,%7}, {%8,%9}, {%0,%1,%2,%3};"
                        : "+f"(acc[mt][nt][0]), "+f"(acc[mt][nt][1]),
                          "+f"(acc[mt][nt][2]), "+f"(acc[mt][nt][3])
                        : "r"(a0), "r"(a1), "r"(a2), "r"(a3),
                          "r"(bf[nt][0]), "r"(bf[nt][1]));
                }
            }
        }
        __syncthreads();
    }

    // reduce sum-of-squares across the 8 staging threads of each row
    #pragma unroll
    for (int o = 4; o; o >>= 1) {
        #pragma unroll
        for (int i = 0; i < 4; i++) ssA[i] += __shfl_xor_sync(0xffffffffu, ssA[i], o);
        #pragma unroll
        for (int i = 0; i < 2; i++) ssB[i] += __shfl_xor_sync(0xffffffffu, ssB[i], o);
    }
    if ((t & 7) == 0) {
        #pragma unroll
        for (int i = 0; i < 4; i++) ran[lr + 32*i] = rsqrtf(ssA[i]);
        #pragma unroll
        for (int i = 0; i < 2; i++) rbn[lr + 32*i] = rsqrtf(ssB[i]);
    }
    __syncthreads();

    size_t base = (size_t)b * NN * NN;
    unsigned* Ew = g_Ebf + (size_t)b * (NN * NN / 2);
    #pragma unroll
    for (int mt = 0; mt < 2; mt++) {
        #pragma unroll
        for (int nt = 0; nt < 4; nt++) {
            int ml = wm + mt*16 + (lane >> 2);
            int nl = wn + nt*8 + (lane & 3)*2;
            int m = m0 + ml, n = n0 + nl;
            float r0 = ran[ml];
            float r2 = ran[ml + 8];
            float rb0 = rbn[nl], rb1 = rbn[nl + 1];
            float c0 = 1.0f - acc[mt][nt][0] * r0 * rb0;
            float c1 = 1.0f - acc[mt][nt][1] * r0 * rb1;
            float c2 = 1.0f - acc[mt][nt][2] * r2 * rb0;
            float c3 = 1.0f - acc[mt][nt][3] * r2 * rb1;
            *(float2*)&Cout[base + (size_t)m*NN + n]     = make_float2(c0, c1);
            *(float2*)&Cout[base + (size_t)(m+8)*NN + n] = make_float2(c2, c3);
            __nv_bfloat162 p01 = __floats2bfloat162_rn(__expf(-INV_EPS*c0), __expf(-INV_EPS*c1));
            __nv_bfloat162 p23 = __floats2bfloat162_rn(__expf(-INV_EPS*c2), __expf(-INV_EPS*c3));
            Ew[m*256 + (n >> 1)]     = *(unsigned*)&p01;
            Ew[(m+8)*256 + (n >> 1)] = *(unsigned*)&p23;
        }
    }
}

// ---------------- 2) persistent Sinkhorn kernel (cluster of 4) ---------------
#define SM_E     0
#define SM_COLP  131072                       // 16 warps x 512 floats = 32768
#define SM_COLR  (SM_COLP + 32768)            // 2 x 512 floats (double buffer)
#define SM_W     (SM_COLR + 4096)
#define SM_Q     (SM_W + 2048)
#define SM_P     (SM_Q + 2048)
#define SM_SU    (SM_P + 512)
#define SM_CRED  (SM_SU + 512)
#define SM_TOT   (SM_CRED + 64 + 64)

__device__ __forceinline__ unsigned smem_u32(const void* p) {
    unsigned a;
    asm("{ .reg .u64 t; cvta.to.shared.u64 t, %1; cvt.u32.u64 %0, t; }"
        : "=r"(a) : "l"(p));
    return a;
}
__device__ __forceinline__ float dsmem_ld(unsigned local_addr, unsigned rank) {
    unsigned rem; float v;
    asm volatile("mapa.shared::cluster.u32 %0, %1, %2;" : "=r"(rem)
                 : "r"(local_addr), "r"(rank));
    asm volatile("ld.shared::cluster.f32 %0, [%1];" : "=f"(v) : "r"(rem));
    return v;
}

__global__ void __cluster_dims__(4, 1, 1) __launch_bounds__(PTHREADS, 1)
sink_kernel(float* __restrict__ cost, float* __restrict__ pi,
            const float* __restrict__ C) {
    extern __shared__ unsigned char sm[];
    unsigned* Eu  = (unsigned*)(sm + SM_E);      // [128][256] words (2 bf16/word)
    float* colp   = (float*)(sm + SM_COLP);      // [16][512]
    float* colr   = (float*)(sm + SM_COLR);      // [2][512]
    float* w      = (float*)(sm + SM_W);         // [512]
    float* q      = (float*)(sm + SM_Q);         // [512]
    float* p      = (float*)(sm + SM_P);         // [128]
    float* su     = (float*)(sm + SM_SU);        // [128]
    float* cred   = (float*)(sm + SM_CRED);      // [16]

    int g = blockIdx.x, b = g >> 2;
    unsigned rank;
    asm("mov.u32 %0, %%cluster_ctarank;" : "=r"(rank));
    int row0 = (int)rank * 128;
    int t = threadIdx.x, warp = t >> 5, lane = t & 31;
    unsigned sb = smem_u32(sm);

    // prologue: bf16 E tile gmem -> smem (raw 128KB copy)
    {
        const uint4* Eg4 = (const uint4*)(g_Ebf + ((size_t)b * NN + row0) * 256);
        uint4* Es4 = (uint4*)Eu;
        #pragma unroll
        for (int i = t; i < 8192; i += PTHREADS) Es4[i] = Eg4[i];
    }
    if (t < 512) { w[t] = 1.f; q[t] = 1.f; }
    if (t < 128) p[t] = 1.f;
    __syncthreads();

    for (int it = 0; it < ITERS; it++) {
        // lane owns column pairs {2*lane + 64k, 2*lane+64k+1}, k=0..7
        float wreg[16];
        #pragma unroll
        for (int k = 0; k < 8; k++) {
            float2 wp = *(const float2*)&w[2*lane + 64*k];
            wreg[2*k] = wp.x; wreg[2*k+1] = wp.y;
        }
        float colacc[16];
        #pragma unroll
        for (int i = 0; i < 16; i++) colacc[i] = 0.f;

        // 8 rows per warp, processed in pairs (dual shuffle chains)
        #pragma unroll
        for (int rg = 0; rg < 4; rg++) {
            int rowA = warp * 8 + rg * 2;
            int rowB = rowA + 1;
            const unsigned* EA = &Eu[rowA * 256];
            const unsigned* EB = &Eu[rowB * 256];
            unsigned ea[8], eb[8];
            #pragma unroll
            for (int k = 0; k < 8; k++) ea[k] = EA[lane + 32*k];
            #pragma unroll
            for (int k = 0; k < 8; k++) eb[k] = EB[lane + 32*k];

            float dA0=0.f, dA1=0.f, dB0=0.f, dB1=0.f;
            #pragma unroll
            for (int k = 0; k < 8; k++) {
                dA0 += __uint_as_float(ea[k] << 16)         * wreg[2*k];
                dA1 += __uint_as_float(ea[k] & 0xffff0000u) * wreg[2*k+1];
                dB0 += __uint_as_float(eb[k] << 16)         * wreg[2*k];
                dB1 += __uint_as_float(eb[k] & 0xffff0000u) * wreg[2*k+1];
            }
            float dA = dA0 + dA1, dB = dB0 + dB1;
            #pragma unroll
            for (int o = 16; o; o >>= 1) {
                dA += __shfl_xor_sync(0xffffffffu, dA, o);
                dB += __shfl_xor_sync(0xffffffffu, dB, o);
            }
            float pA = p[rowA], pB = p[rowB];
            float uA = MARG / (pA * dA + TINYF);
            float uB = MARG / (pB * dB + TINYF);
            float pnA = pA * uA, pnB = pB * uB;
            if (lane == 0) {
                p[rowA] = pnA; p[rowB] = pnB;
                if (it == ITERS - 1) { su[rowA] = uA * pnA; su[rowB] = uB * pnB; }
            }
            #pragma unroll
            for (int k = 0; k < 8; k++) {
                colacc[2*k]   += __uint_as_float(ea[k] << 16)         * pnA
                               + __uint_as_float(eb[k] << 16)         * pnB;
                colacc[2*k+1] += __uint_as_float(ea[k] & 0xffff0000u) * pnA
                               + __uint_as_float(eb[k] & 0xffff0000u) * pnB;
            }
        }
        // stage per-warp column partials
        #pragma unroll
        for (int k = 0; k < 8; k++)
            *(float2*)&colp[warp * 512 + 2*lane + 64*k] =
                make_float2(colacc[2*k], colacc[2*k+1]);
        __syncthreads();
        // block column reduce -> colr[it&1]
        if (t < 512) {
            float s = 0.f;
            #pragma unroll
            for (int j = 0; j < 16; j++) s += colp[j * 512 + t];
            colr[(it & 1) * 512 + t] = s;
        }
        // one cluster barrier: partials visible cluster-wide
        asm volatile("barrier.cluster.arrive.aligned;" ::: "memory");
        asm volatile("barrier.cluster.wait.aligned;"   ::: "memory");
        // column update via DSMEM (deterministic rank order, redundant per CTA)
        if (t < 512) {
            unsigned addr = sb + SM_COLR + (unsigned)(it & 1) * 2048 + t * 4;
            float s0 = dsmem_ld(addr, 0);
            float s1 = dsmem_ld(addr, 1);
            float s2 = dsmem_ld(addr, 2);
            float s3 = dsmem_ld(addr, 3);
            float tot = (s0 + s1) + (s2 + s3);
            float qold = q[t];
            float v = MARG / (qold * tot + TINYF);
            float qn = qold * v;
            q[t] = qn;
            w[t] = qn * v;      // w = v*q
        }
        __syncthreads();
    }

    // final: e = expf(-10*C) fp32 (recomputed — full precision for pi);
    // pi = e * su[row] * w[col];  cost = sum(pi * C)
    size_t base = ((size_t)b * NN + row0) * NN;
    float csum = 0.f;
    for (int r = 0; r < 8; r++) {
        int row = warp * 8 + r;
        float s_u = su[row];
        const float4* C4 = (const float4*)(C + base + (size_t)row * NN);
        float4*       P4 = (float4*)(pi + base + (size_t)row * NN);
        #pragma unroll
        for (int k = 0; k < 4; k++) {
            int idx = lane + 32*k;
            float4 cc = C4[idx];
            float4 wv = *(const float4*)&w[4*lane + 128*k];
            float4 pv;
            pv.x = __expf(-INV_EPS*cc.x) * s_u * wv.x;
            pv.y = __expf(-INV_EPS*cc.y) * s_u * wv.y;
            pv.z = __expf(-INV_EPS*cc.z) * s_u * wv.z;
            pv.w = __expf(-INV_EPS*cc.w) * s_u * wv.w;
            csum += pv.x*cc.x + pv.y*cc.y + pv.z*cc.z + pv.w*cc.w;
            asm volatile("st.global.cs.v4.f32 [%0], {%1,%2,%3,%4};"
                         :: "l"(P4 + idx), "f"(pv.x), "f"(pv.y), "f"(pv.z), "f"(pv.w)
                         : "memory");
        }
    }
    #pragma unroll
    for (int o = 16; o; o >>= 1) csum += __shfl_xor_sync(0xffffffffu, csum, o);
    if (lane == 0) cred[warp] = csum;
    __syncthreads();
    if (t == 0) {
        float s = 0.f;
        #pragma unroll
        for (int i = 0; i < 16; i++) s += cred[i];
        cred[0] = s;                 // per-CTA cost partial, staged for DSMEM
    }
    // cluster barrier: cred[0] visible cluster-wide; protects smem lifetime
    asm volatile("barrier.cluster.arrive.aligned;" ::: "memory");
    asm volatile("barrier.cluster.wait.aligned;"   ::: "memory");
    if (rank == 0 && t == 0) {
        unsigned addr = sb + SM_CRED;
        float s0 = dsmem_ld(addr, 0);
        float s1 = dsmem_ld(addr, 1);
        float s2 = dsmem_ld(addr, 2);
        float s3 = dsmem_ld(addr, 3);
        cost[b] = (s0 + s1) + (s2 + s3);
    }
    asm volatile("barrier.cluster.arrive.aligned;" ::: "memory");
    asm volatile("barrier.cluster.wait.aligned;"   ::: "memory");
}

// ---------------- launch ------------------------------------------------------
extern "C" void kernel_launch(void* const* d_in, const int* in_sizes, int n_in,
                              void* d_out, int out_size) {
    const float* x = (const float*)d_in[0];
    const float* y = (const float*)d_in[1];
    float* out  = (float*)d_out;
    float* cost = out;
    float* pi   = out + NB;
    float* C    = out + NB + (size_t)NB * NN * NN;

    static int smem_set = 0;
    if (!smem_set) {
        cudaFuncSetAttribute(sink_kernel,
                             cudaFuncAttributeMaxDynamicSharedMemorySize, SM_TOT);
        smem_set = 1;
    }

    gemm_kernel<<<dim3(8, 4, NB), 256>>>(C, x, y);
    sink_kernel<<<PGRID, PTHREADS, SM_TOT>>>(cost, pi, C);
}

// round 13
// speedup vs baseline: 1.6044x; 1.0197x over previous
#include <cuda_runtime.h>
#include <cuda_bf16.h>
#include <cstdint>
#include <math.h>

#define NB 32
#define NN 512
#define DD 256
#define INV_EPS 10.0f
#define TINYF 1e-16f
#define MARG (1.0f/512.0f)
#define ITERS 15
#define PGRID 128      // 32 clusters x 4 CTAs; 1 block/SM
#define PTHREADS 512

// ---------------- helpers -----------------------------------------------------
__device__ __forceinline__ unsigned smem_u32(const void* p) {
    unsigned a;
    asm("{ .reg .u64 t; cvta.to.shared.u64 t, %1; cvt.u32.u64 %0, t; }"
        : "=r"(a) : "l"(p));
    return a;
}
__device__ __forceinline__ float dsmem_ld(unsigned local_addr, unsigned rank) {
    unsigned rem; float v;
    asm volatile("mapa.shared::cluster.u32 %0, %1, %2;" : "=r"(rem)
                 : "r"(local_addr), "r"(rank));
    asm volatile("ld.shared::cluster.f32 %0, [%1];" : "=f"(v) : "r"(rem));
    return v;
}
__device__ __forceinline__ unsigned f2tf32(float f) {
    unsigned r;
    asm("cvt.rna.tf32.f32 %0, %1;" : "=r"(r) : "f"(f));
    return r;
}

// ---------------- smem layout -------------------------------------------------
// GEMM phase reuses the colp/colr region (36KB) as tf32 staging buffers,
// the p region as ry and the su region as rx.
#define SM_E     0                            // 128KB: E tile, bf16x2 words
#define SM_COLP  131072                       // iter: [16][512] col partials
#define SM_COLR  (SM_COLP + 32768)            // iter: [2][512] double buffer
#define SM_AS    SM_COLP                      // gemm: As[128][36] f32 (18432B)
#define SM_BS    (SM_COLP + 18432)            // gemm: Bs[128][36] f32 (18432B)
#define SM_W     (SM_COLR + 4096)
#define SM_Q     (SM_W + 2048)
#define SM_P     (SM_Q + 2048)                // gemm: ry[128]
#define SM_SU    (SM_P + 512)                 // gemm: rx[128]
#define SM_CRED  (SM_SU + 512)
#define SM_TOT   (SM_CRED + 64 + 64)

// ---------------- fused kernel: GEMM + Sinkhorn + epilogue -------------------
__global__ void __cluster_dims__(4, 1, 1) __launch_bounds__(PTHREADS, 1)
sink_kernel(float* __restrict__ cost, float* __restrict__ pi,
            float* __restrict__ C,
            const float* __restrict__ x, const float* __restrict__ y) {
    extern __shared__ unsigned char sm[];
    unsigned* Eu  = (unsigned*)(sm + SM_E);      // [128][256] words (2 bf16/word)
    float* colp   = (float*)(sm + SM_COLP);      // [16][512]
    float* colr   = (float*)(sm + SM_COLR);      // [2][512]
    float (*As)[36] = (float(*)[36])(sm + SM_AS);
    float (*Bs)[36] = (float(*)[36])(sm + SM_BS);
    float* w      = (float*)(sm + SM_W);         // [512]
    float* q      = (float*)(sm + SM_Q);         // [512]
    float* p      = (float*)(sm + SM_P);         // [128]  (gemm: ry)
    float* su     = (float*)(sm + SM_SU);        // [128]  (gemm: rx)
    float* cred   = (float*)(sm + SM_CRED);      // [16]
    float* rys    = p;
    float* rxs    = su;

    int g = blockIdx.x, b = g >> 2;
    unsigned rank;
    asm("mov.u32 %0, %%cluster_ctarank;" : "=r"(rank));
    int row0 = (int)rank * 128;
    int t = threadIdx.x, warp = t >> 5, lane = t & 31;
    unsigned sb = smem_u32(sm);

    // ================= Phase 1: GEMM (tile 128x512, tf32 mma.sync) ==========
    {
        int wm = (warp >> 2) * 32;               // warp m offset 0..96
        int wn = (warp & 3) * 32;                // warp n offset 0..96
        int arow = t >> 2;                       // 0..127 staging row
        int ac8  = (t & 3) * 8;                  // staging col chunk
        float ssA = 0.f;
        const float* xrow = x + ((size_t)(b*NN + row0 + arow)) * DD;

        for (int nt0 = 0; nt0 < 4; nt0++) {
            int n0 = nt0 * 128;
            float ssY = 0.f;
            const float* yrow = y + ((size_t)(b*NN + n0 + arow)) * DD;

            float acc[2][4][4];
            #pragma unroll
            for (int i=0;i<2;i++)
                #pragma unroll
                for (int j=0;j<4;j++)
                    #pragma unroll
                    for (int k=0;k<4;k++) acc[i][j][k] = 0.f;

            for (int s = 0; s < 8; s++) {
                // stage A[128][32] + B[128][32] as tf32
                float4 a0 = *(const float4*)(xrow + s*32 + ac8);
                float4 a1 = *(const float4*)(xrow + s*32 + ac8 + 4);
                float4 b0 = *(const float4*)(yrow + s*32 + ac8);
                float4 b1 = *(const float4*)(yrow + s*32 + ac8 + 4);
                if (nt0 == 0)
                    ssA += a0.x*a0.x + a0.y*a0.y + a0.z*a0.z + a0.w*a0.w
                         + a1.x*a1.x + a1.y*a1.y + a1.z*a1.z + a1.w*a1.w;
                ssY += b0.x*b0.x + b0.y*b0.y + b0.z*b0.z + b0.w*b0.w
                     + b1.x*b1.x + b1.y*b1.y + b1.z*b1.z + b1.w*b1.w;
                As[arow][ac8+0] = __uint_as_float(f2tf32(a0.x));
                As[arow][ac8+1] = __uint_as_float(f2tf32(a0.y));
                As[arow][ac8+2] = __uint_as_float(f2tf32(a0.z));
                As[arow][ac8+3] = __uint_as_float(f2tf32(a0.w));
                As[arow][ac8+4] = __uint_as_float(f2tf32(a1.x));
                As[arow][ac8+5] = __uint_as_float(f2tf32(a1.y));
                As[arow][ac8+6] = __uint_as_float(f2tf32(a1.z));
                As[arow][ac8+7] = __uint_as_float(f2tf32(a1.w));
                Bs[arow][ac8+0] = __uint_as_float(f2tf32(b0.x));
                Bs[arow][ac8+1] = __uint_as_float(f2tf32(b0.y));
                Bs[arow][ac8+2] = __uint_as_float(f2tf32(b0.z));
                Bs[arow][ac8+3] = __uint_as_float(f2tf32(b0.w));
                Bs[arow][ac8+4] = __uint_as_float(f2tf32(b1.x));
                Bs[arow][ac8+5] = __uint_as_float(f2tf32(b1.y));
                Bs[arow][ac8+6] = __uint_as_float(f2tf32(b1.z));
                Bs[arow][ac8+7] = __uint_as_float(f2tf32(b1.w));
                __syncthreads();
                #pragma unroll
                for (int ks = 0; ks < 4; ks++) {
                    int kc = ks * 8 + (lane & 3);
                    unsigned bf[4][2];
                    #pragma unroll
                    for (int nx = 0; nx < 4; nx++) {
                        int nb = wn + nx*8 + (lane >> 2);
                        bf[nx][0] = __float_as_uint(Bs[nb][kc]);
                        bf[nx][1] = __float_as_uint(Bs[nb][kc + 4]);
                    }
                    #pragma unroll
                    for (int mt = 0; mt < 2; mt++) {
                        int ma = wm + mt*16 + (lane >> 2);
                        unsigned fa0 = __float_as_uint(As[ma    ][kc]);
                        unsigned fa1 = __float_as_uint(As[ma + 8][kc]);
                        unsigned fa2 = __float_as_uint(As[ma    ][kc + 4]);
                        unsigned fa3 = __float_as_uint(As[ma + 8][kc + 4]);
                        #pragma unroll
                        for (int nx = 0; nx < 4; nx++) {
                            asm volatile(
                                "mma.sync.aligned.m16n8k8.row.col.f32.tf32.tf32.f32 "
                                "{%0,%1,%2,%3}, {%4,%5,%6,%7}, {%8,%9}, {%0,%1,%2,%3};"
                                : "+f"(acc[mt][nx][0]), "+f"(acc[mt][nx][1]),
                                  "+f"(acc[mt][nx][2]), "+f"(acc[mt][nx][3])
                                : "r"(fa0), "r"(fa1), "r"(fa2), "r"(fa3),
                                  "r"(bf[nx][0]), "r"(bf[nx][1]));
                        }
                    }
                }
                __syncthreads();
            }
            // reduce ssY (and ssA on first n-tile) across the 4 stager threads/row
            ssY += __shfl_xor_sync(0xffffffffu, ssY, 1);
            ssY += __shfl_xor_sync(0xffffffffu, ssY, 2);
            if (nt0 == 0) {
                ssA += __shfl_xor_sync(0xffffffffu, ssA, 1);
                ssA += __shfl_xor_sync(0xffffffffu, ssA, 2);
            }
            if ((t & 3) == 0) {
                rys[arow] = rsqrtf(ssY);
                if (nt0 == 0) rxs[arow] = rsqrtf(ssA);
            }
            __syncthreads();
            // epilogue: C fp32 -> gmem, E bf16 -> smem Eu
            size_t cb = (size_t)b * NN * NN + (size_t)(row0) * NN;
            #pragma unroll
            for (int mt = 0; mt < 2; mt++) {
                #pragma unroll
                for (int nx = 0; nx < 4; nx++) {
                    int ml = wm + mt*16 + (lane >> 2);
                    int nl = wn + nx*8 + (lane & 3)*2;
                    float rx0 = rxs[ml], rx2 = rxs[ml + 8];
                    float ry0 = rys[nl], ry1 = rys[nl + 1];
                    float c0 = 1.0f - acc[mt][nx][0] * rx0 * ry0;
                    float c1 = 1.0f - acc[mt][nx][1] * rx0 * ry1;
                    float c2 = 1.0f - acc[mt][nx][2] * rx2 * ry0;
                    float c3 = 1.0f - acc[mt][nx][3] * rx2 * ry1;
                    *(float2*)&C[cb + (size_t)ml*NN + n0 + nl]     = make_float2(c0, c1);
                    *(float2*)&C[cb + (size_t)(ml+8)*NN + n0 + nl] = make_float2(c2, c3);
                    __nv_bfloat162 e01 = __floats2bfloat162_rn(__expf(-INV_EPS*c0), __expf(-INV_EPS*c1));
                    __nv_bfloat162 e23 = __floats2bfloat162_rn(__expf(-INV_EPS*c2), __expf(-INV_EPS*c3));
                    Eu[ml*256 + ((n0 + nl) >> 1)]     = *(unsigned*)&e01;
                    Eu[(ml+8)*256 + ((n0 + nl) >> 1)] = *(unsigned*)&e23;
                }
            }
            __syncthreads();
        }
    }

    // ================= Phase 2: Sinkhorn iterations ==========================
    if (t < 512) { w[t] = 1.f; q[t] = 1.f; }
    if (t < 128) p[t] = 1.f;
    __syncthreads();

    for (int it = 0; it < ITERS; it++) {
        float wreg[16];
        #pragma unroll
        for (int k = 0; k < 8; k++) {
            float2 wp = *(const float2*)&w[2*lane + 64*k];
            wreg[2*k] = wp.x; wreg[2*k+1] = wp.y;
        }
        float colacc[16];
        #pragma unroll
        for (int i = 0; i < 16; i++) colacc[i] = 0.f;

        #pragma unroll
        for (int rg = 0; rg < 4; rg++) {
            int rowA = warp * 8 + rg * 2;
            int rowB = rowA + 1;
            const unsigned* EA = &Eu[rowA * 256];
            const unsigned* EB = &Eu[rowB * 256];
            unsigned ea[8], eb[8];
            #pragma unroll
            for (int k = 0; k < 8; k++) ea[k] = EA[lane + 32*k];
            #pragma unroll
            for (int k = 0; k < 8; k++) eb[k] = EB[lane + 32*k];

            float dA0=0.f, dA1=0.f, dB0=0.f, dB1=0.f;
            #pragma unroll
            for (int k = 0; k < 8; k++) {
                dA0 += __uint_as_float(ea[k] << 16)         * wreg[2*k];
                dA1 += __uint_as_float(ea[k] & 0xffff0000u) * wreg[2*k+1];
                dB0 += __uint_as_float(eb[k] << 16)         * wreg[2*k];
                dB1 += __uint_as_float(eb[k] & 0xffff0000u) * wreg[2*k+1];
            }
            float dA = dA0 + dA1, dB = dB0 + dB1;
            #pragma unroll
            for (int o = 16; o; o >>= 1) {
                dA += __shfl_xor_sync(0xffffffffu, dA, o);
                dB += __shfl_xor_sync(0xffffffffu, dB, o);
            }
            float pA = p[rowA], pB = p[rowB];
            float uA = MARG / (pA * dA + TINYF);
            float uB = MARG / (pB * dB + TINYF);
            float pnA = pA * uA, pnB = pB * uB;
            if (lane == 0) {
                p[rowA] = pnA; p[rowB] = pnB;
                if (it == ITERS - 1) { su[rowA] = uA * pnA; su[rowB] = uB * pnB; }
            }
            #pragma unroll
            for (int k = 0; k < 8; k++) {
                colacc[2*k]   += __uint_as_float(ea[k] << 16)         * pnA
                               + __uint_as_float(eb[k] << 16)         * pnB;
                colacc[2*k+1] += __uint_as_float(ea[k] & 0xffff0000u) * pnA
                               + __uint_as_float(eb[k] & 0xffff0000u) * pnB;
            }
        }
        #pragma unroll
        for (int k = 0; k < 8; k++)
            *(float2*)&colp[warp * 512 + 2*lane + 64*k] =
                make_float2(colacc[2*k], colacc[2*k+1]);
        __syncthreads();
        if (t < 512) {
            float s = 0.f;
            #pragma unroll
            for (int j = 0; j < 16; j++) s += colp[j * 512 + t];
            colr[(it & 1) * 512 + t] = s;
        }
        asm volatile("barrier.cluster.arrive.aligned;" ::: "memory");
        asm volatile("barrier.cluster.wait.aligned;"   ::: "memory");
        if (t < 512) {
            unsigned addr = sb + SM_COLR + (unsigned)(it & 1) * 2048 + t * 4;
            float s0 = dsmem_ld(addr, 0);
            float s1 = dsmem_ld(addr, 1);
            float s2 = dsmem_ld(addr, 2);
            float s3 = dsmem_ld(addr, 3);
            float tot = (s0 + s1) + (s2 + s3);
            float qold = q[t];
            float v = MARG / (qold * tot + TINYF);
            float qn = qold * v;
            q[t] = qn;
            w[t] = qn * v;
        }
        __syncthreads();
    }

    // ================= Phase 3: pi + cost epilogue ===========================
    size_t base = ((size_t)b * NN + row0) * NN;
    float csum = 0.f;
    for (int r = 0; r < 8; r++) {
        int row = warp * 8 + r;
        float s_u = su[row];
        const float4* C4 = (const float4*)(C + base + (size_t)row * NN);
        float4*       P4 = (float4*)(pi + base + (size_t)row * NN);
        #pragma unroll
        for (int k = 0; k < 4; k++) {
            int idx = lane + 32*k;
            float4 cc = C4[idx];
            float4 wv = *(const float4*)&w[4*lane + 128*k];
            float4 pv;
            pv.x = __expf(-INV_EPS*cc.x) * s_u * wv.x;
            pv.y = __expf(-INV_EPS*cc.y) * s_u * wv.y;
            pv.z = __expf(-INV_EPS*cc.z) * s_u * wv.z;
            pv.w = __expf(-INV_EPS*cc.w) * s_u * wv.w;
            csum += pv.x*cc.x + pv.y*cc.y + pv.z*cc.z + pv.w*cc.w;
            asm volatile("st.global.cs.v4.f32 [%0], {%1,%2,%3,%4};"
                         :: "l"(P4 + idx), "f"(pv.x), "f"(pv.y), "f"(pv.z), "f"(pv.w)
                         : "memory");
        }
    }
    #pragma unroll
    for (int o = 16; o; o >>= 1) csum += __shfl_xor_sync(0xffffffffu, csum, o);
    if (lane == 0) cred[warp] = csum;
    __syncthreads();
    if (t == 0) {
        float s = 0.f;
        #pragma unroll
        for (int i = 0; i < 16; i++) s += cred[i];
        cred[0] = s;
    }
    asm volatile("barrier.cluster.arrive.aligned;" ::: "memory");
    asm volatile("barrier.cluster.wait.aligned;"   ::: "memory");
    if (rank == 0 && t == 0) {
        unsigned addr = sb + SM_CRED;
        float s0 = dsmem_ld(addr, 0);
        float s1 = dsmem_ld(addr, 1);
        float s2 = dsmem_ld(addr, 2);
        float s3 = dsmem_ld(addr, 3);
        cost[b] = (s0 + s1) + (s2 + s3);
    }
    asm volatile("barrier.cluster.arrive.aligned;" ::: "memory");
    asm volatile("barrier.cluster.wait.aligned;"   ::: "memory");
}

// ---------------- launch ------------------------------------------------------
extern "C" void kernel_launch(void* const* d_in, const int* in_sizes, int n_in,
                              void* d_out, int out_size) {
    const float* x = (const float*)d_in[0];
    const float* y = (const float*)d_in[1];
    float* out  = (float*)d_out;
    float* cost = out;
    float* pi   = out + NB;
    float* C    = out + NB + (size_t)NB * NN * NN;

    static int smem_set = 0;
    if (!smem_set) {
        cudaFuncSetAttribute(sink_kernel,
                             cudaFuncAttributeMaxDynamicSharedMemorySize, SM_TOT);
        smem_set = 1;
    }

    sink_kernel<<<PGRID, PTHREADS, SM_TOT>>>(cost, pi, C, x, y);
}